// round 5
// baseline (speedup 1.0000x reference)
#include <cuda_runtime.h>
#include <cstdint>

#define NN 2048
#define HH 1024
#define TSTEPS (NN + NN/8)   // 2304
#define C1 0.015625f          // ALPHA(0.5) / sqrt(1024)

// ---------------- static scratch (no allocations allowed) ----------------
__device__ float g_K[(size_t)NN * HH];       // 8 MB : K = E@Wk^T + bk
__device__ float g_Q[(size_t)NN * HH];       // 8 MB : Q = E@Wq1^T + bq
__device__ float g_P[(size_t)NN * NN];       // 16 MB: P = C1 * Q @ K^T
__device__ float g_Wq1[(size_t)HH * HH];     // 4 MB : packed Wq[:, :1024]
__device__ float g_wqload[HH];               // Wq[:, 1024]
__device__ float g_su[NN];                   // C1 * K @ wq_load

// ---------------- pack Wq (stride 1026 -> 1024, extract load column) -----
__global__ void pack_wq_kernel(const float* __restrict__ Wq) {
    int idx = blockIdx.x * blockDim.x + threadIdx.x;
    if (idx < HH * HH) {
        int i = idx >> 10;
        int h = idx & 1023;
        g_Wq1[idx] = Wq[i * (HH + 2) + h];
    }
    if (idx < HH) {
        g_wqload[idx] = Wq[idx * (HH + 2) + HH];
    }
}

// ---------------- generic NT GEMM: C = scale*(A@B^T) + bias[col] ---------
// A: [M,Kd] row-major (lda), B: [N,Kd] row-major (ldb), C: [M,N] (ldc)
// BM=BN=128, BK=16, 256 threads, 8x8 per thread, register prefetch.
#define BM 128
#define BN 128
#define BK 16

__global__ __launch_bounds__(256, 2)
void gemm_kernel(int mode, const float* __restrict__ Ain,
                 const float* __restrict__ Bin, const float* __restrict__ biasin) {
    const float* A; const float* B; const float* bias; float* C;
    int lda, ldb, ldc; float scale;
    if (mode == 0)      { A = Ain; lda = HH; B = Bin;    ldb = HH; bias = biasin; C = g_K; ldc = HH; scale = 1.0f; }
    else if (mode == 1) { A = Ain; lda = HH; B = g_Wq1;  ldb = HH; bias = biasin; C = g_Q; ldc = HH; scale = 1.0f; }
    else                { A = g_Q; lda = HH; B = g_K;    ldb = HH; bias = nullptr; C = g_P; ldc = NN; scale = C1;  }

    __shared__ float As[BK][BM + 1];
    __shared__ float Bs[BK][BN + 1];

    const int tid = threadIdx.x;
    const int m0 = blockIdx.y * BM;
    const int n0 = blockIdx.x * BN;
    const int tx = tid & 15;    // n direction (16)
    const int ty = tid >> 4;    // m direction (16)

    const int lr = tid >> 2;            // 0..63 (row within first half of tile)
    const int lk = (tid & 3) * 4;       // k-vector offset: 0,4,8,12

    const float* Aptr = A + (size_t)(m0 + lr) * lda + lk;
    const float* Bptr = B + (size_t)(n0 + lr) * ldb + lk;

    float acc[8][8];
#pragma unroll
    for (int i = 0; i < 8; ++i)
#pragma unroll
        for (int j = 0; j < 8; ++j) acc[i][j] = 0.0f;

    const int Kd = HH;
    // prefetch first tile into registers
    float4 a0 = *(const float4*)(Aptr);
    float4 a1 = *(const float4*)(Aptr + (size_t)64 * lda);
    float4 b0 = *(const float4*)(Bptr);
    float4 b1 = *(const float4*)(Bptr + (size_t)64 * ldb);

    for (int k0 = 0; k0 < Kd; k0 += BK) {
        __syncthreads();
        As[lk + 0][lr]      = a0.x; As[lk + 1][lr]      = a0.y; As[lk + 2][lr]      = a0.z; As[lk + 3][lr]      = a0.w;
        As[lk + 0][lr + 64] = a1.x; As[lk + 1][lr + 64] = a1.y; As[lk + 2][lr + 64] = a1.z; As[lk + 3][lr + 64] = a1.w;
        Bs[lk + 0][lr]      = b0.x; Bs[lk + 1][lr]      = b0.y; Bs[lk + 2][lr]      = b0.z; Bs[lk + 3][lr]      = b0.w;
        Bs[lk + 0][lr + 64] = b1.x; Bs[lk + 1][lr + 64] = b1.y; Bs[lk + 2][lr + 64] = b1.z; Bs[lk + 3][lr + 64] = b1.w;
        __syncthreads();
        if (k0 + BK < Kd) {
            a0 = *(const float4*)(Aptr + k0 + BK);
            a1 = *(const float4*)(Aptr + (size_t)64 * lda + k0 + BK);
            b0 = *(const float4*)(Bptr + k0 + BK);
            b1 = *(const float4*)(Bptr + (size_t)64 * ldb + k0 + BK);
        }
#pragma unroll
        for (int kk = 0; kk < BK; ++kk) {
            float a[8], b[8];
#pragma unroll
            for (int i = 0; i < 8; ++i) a[i] = As[kk][ty * 8 + i];
#pragma unroll
            for (int j = 0; j < 8; ++j) b[j] = Bs[kk][tx * 8 + j];
#pragma unroll
            for (int i = 0; i < 8; ++i)
#pragma unroll
                for (int j = 0; j < 8; ++j) acc[i][j] += a[i] * b[j];
        }
    }

    float bv[8];
#pragma unroll
    for (int j = 0; j < 8; ++j) bv[j] = bias ? bias[n0 + tx * 8 + j] : 0.0f;
#pragma unroll
    for (int i = 0; i < 8; ++i) {
        float* crow = C + (size_t)(m0 + ty * 8 + i) * ldc + n0 + tx * 8;
#pragma unroll
        for (int j = 0; j < 8; ++j) crow[j] = scale * acc[i][j] + bv[j];
    }
}

// ---------------- su[n] = C1 * dot(K[n], wq_load) ------------------------
__global__ void su_kernel() {
    int row = blockIdx.x * 8 + (threadIdx.x >> 5);
    int lane = threadIdx.x & 31;
    const float* kr = g_K + (size_t)row * HH;
    float acc = 0.0f;
    for (int i = lane; i < HH; i += 32) acc += kr[i] * g_wqload[i];
#pragma unroll
    for (int off = 16; off; off >>= 1) acc += __shfl_down_sync(0xffffffffu, acc, off);
    if (lane == 0) g_su[row] = C1 * acc;
}

// ---------------- sequential greedy decode (1 block, 256 threads) --------
__global__ __launch_bounds__(256, 1)
void decode_kernel(const float* __restrict__ demands,
                   const int* __restrict__ cap_p,
                   const int* __restrict__ dep_p,
                   float* __restrict__ out) {
    const int tid = threadIdx.x;
    const int lane = tid & 31;
    const int warp = tid >> 5;
    const float cap = (float)(*cap_p);
    const int dep = *dep_p;
    const float NEG_INF = __int_as_float(0xff800000);

    __shared__ float s_pv[8];
    __shared__ int   s_pi[8];
    __shared__ int   s_nxt[2];
    __shared__ float s_ld[2];

    // per-thread static state: 8 nodes each
    const int nbase = tid * 8;
    float d[8], su[8];
#pragma unroll
    for (int j = 0; j < 8; ++j) { d[j] = demands[nbase + j]; su[j] = g_su[nbase + j]; }

    unsigned vis = 0;
    if ((dep >> 3) == tid) vis |= 1u << (dep & 7);
    float load = cap;
    int last = dep;

    if (tid == 0) out[0] = (float)dep;

    for (int t = 0; t < TSTEPS; ++t) {
        const float sload = load / cap;
        const float4* prow = reinterpret_cast<const float4*>(g_P + (size_t)last * NN);
        float4 p0 = prow[tid * 2 + 0];
        float4 p1 = prow[tid * 2 + 1];
        float pv[8] = {p0.x, p0.y, p0.z, p0.w, p1.x, p1.y, p1.z, p1.w};

        float best = NEG_INF;
        int bi = NN;
#pragma unroll
        for (int j = 0; j < 8; ++j) {
            float v = pv[j] + sload * su[j];
            bool feas = (((vis >> j) & 1u) == 0u) && (d[j] <= load);
            if (feas && v > best) { best = v; bi = nbase + j; }   // ascending j: first-max kept
        }
        // warp argmax (tie -> lower index, matching jnp.argmax first-occurrence)
#pragma unroll
        for (int off = 16; off; off >>= 1) {
            float ov = __shfl_down_sync(0xffffffffu, best, off);
            int   oi = __shfl_down_sync(0xffffffffu, bi, off);
            if (ov > best || (ov == best && oi < bi)) { best = ov; bi = oi; }
        }
        if (lane == 0) { s_pv[warp] = best; s_pi[warp] = bi; }
        __syncthreads();
        if (tid < 32) {
            float v = (lane < 8) ? s_pv[lane] : NEG_INF;
            int   i = (lane < 8) ? s_pi[lane] : NN;
#pragma unroll
            for (int off = 4; off; off >>= 1) {
                float ov = __shfl_down_sync(0xffffffffu, v, off);
                int   oi = __shfl_down_sync(0xffffffffu, i, off);
                if (ov > v || (ov == v && oi < i)) { v = ov; i = oi; }
            }
            if (lane == 0) {
                bool take = (i < NN);
                int nxt = take ? i : dep;
                s_nxt[t & 1] = nxt;
                s_ld[t & 1]  = take ? (load - demands[i]) : cap;
                out[1 + t] = (float)nxt;
                out[1 + TSTEPS + t] = take ? v : 0.0f;
            }
        }
        __syncthreads();
        int nxt = s_nxt[t & 1];
        load = s_ld[t & 1];
        last = nxt;
        // take <=> nxt != dep (depot is pre-visited, never a candidate)
        if (nxt != dep && (nxt >> 3) == tid) vis |= 1u << (nxt & 7);
    }
}

// ---------------- launcher ----------------------------------------------
extern "C" void kernel_launch(void* const* d_in, const int* in_sizes, int n_in,
                              void* d_out, int out_size) {
    const float* E   = (const float*)d_in[0];   // node_emb [2048,1024]
    const float* dem = (const float*)d_in[1];   // demands  [2048]
    const float* Wq  = (const float*)d_in[2];   // [1024,1026]
    const float* bq  = (const float*)d_in[3];   // [1024]
    const float* Wk  = (const float*)d_in[4];   // [1024,1024]
    const float* bk  = (const float*)d_in[5];   // [1024]
    const int*   cap = (const int*)d_in[6];     // scalar
    const int*   dep = (const int*)d_in[7];     // scalar
    float* out = (float*)d_out;                 // tour[2305] ++ scores[2304] as f32

    pack_wq_kernel<<<(HH * HH + 255) / 256, 256>>>(Wq);

    dim3 g1(HH / BN, NN / BM);                  // 8 x 16
    gemm_kernel<<<g1, 256>>>(0, E, Wk, bk);     // g_K
    gemm_kernel<<<g1, 256>>>(1, E, nullptr, bq);// g_Q (bq folded in)
    su_kernel<<<NN / 8, 256>>>();               // g_su

    dim3 g3(NN / BN, NN / BM);                  // 16 x 16
    gemm_kernel<<<g3, 256>>>(2, nullptr, nullptr, nullptr); // g_P

    decode_kernel<<<1, 256>>>(dem, cap, dep, out);
}

// round 6
// speedup vs baseline: 1.0033x; 1.0033x over previous
#include <cuda_runtime.h>
#include <cstdint>

#define NN 2048
#define HH 1024
#define TSTEPS (NN + NN/8)   // 2304
#define C1 0.015625f          // ALPHA(0.5) / sqrt(1024)

// ---------------- static scratch (no allocations allowed) ----------------
__device__ float g_K[(size_t)NN * HH];       // 8 MB : K = E@Wk^T + bk
__device__ float g_Q[(size_t)NN * HH];       // 8 MB : Q = E@Wq1^T + bq
__device__ float g_P[(size_t)NN * NN];       // 16 MB: P = C1 * Q @ K^T
__device__ float g_Wq1[(size_t)HH * HH];     // 4 MB : packed Wq[:, :1024]
__device__ float g_wqload[HH];               // Wq[:, 1024]
__device__ float g_su[NN];                   // C1 * K @ wq_load

// ---------------- pack Wq (stride 1026 -> 1024, extract load column) -----
__global__ void pack_wq_kernel(const float* __restrict__ Wq) {
    int idx = blockIdx.x * blockDim.x + threadIdx.x;
    if (idx < HH * HH) {
        int i = idx >> 10;
        int h = idx & 1023;
        g_Wq1[idx] = Wq[i * (HH + 2) + h];
    }
    if (idx < HH) {
        g_wqload[idx] = Wq[idx * (HH + 2) + HH];
    }
}

// ---------------- NT GEMM: C = scale*(A@B^T) + bias[col] -----------------
// MODE 0: z=0 -> g_K = E@Wk^T + bk ; z=1 -> g_Q = E@Wq1^T + bq
// MODE 1: g_P = C1 * g_Q @ g_K^T
// 128x128x16 tiles, 256 thr, 8x8/thread as four 4x4 quadrants,
// double-buffered smem (1 sync/tile), conflict-free LDS.128 compute reads.
#define BM 128
#define BN 128
#define BK 16
#define LDS_PAD 4   // 132-float row stride: 16B aligned, store conflicts 2-way only

template<int MODE>
__global__ __launch_bounds__(256, 2)
void gemm_kernel(const float* __restrict__ Ein, const float* __restrict__ Wk,
                 const float* __restrict__ bk, const float* __restrict__ bq)
{
    const float* A; const float* B; const float* bias; float* C;
    int ldc; float scale;
    if (MODE == 0) {
        A = Ein;
        if (blockIdx.z == 0) { B = Wk;    bias = bk; C = g_K; }
        else                 { B = g_Wq1; bias = bq; C = g_Q; }
        ldc = HH; scale = 1.0f;
    } else {
        A = g_Q; B = g_K; bias = nullptr; C = g_P; ldc = NN; scale = C1;
    }
    const int lda = HH, ldb = HH;

    __shared__ float As[2][BK][BM + LDS_PAD];
    __shared__ float Bs[2][BK][BN + LDS_PAD];

    const int tid = threadIdx.x;
    const int m0 = blockIdx.y * BM;
    const int n0 = blockIdx.x * BN;
    const int tx = tid & 15;    // n quadrant base: tx*4 / 64+tx*4
    const int ty = tid >> 4;    // m quadrant base: ty*4 / 64+ty*4

    const int lr = tid >> 2;            // 0..63
    const int lk = (tid & 3) * 4;       // 0,4,8,12

    const float* Aptr = A + (size_t)(m0 + lr) * lda + lk;
    const float* Bptr = B + (size_t)(n0 + lr) * ldb + lk;

    float acc[8][8];
#pragma unroll
    for (int i = 0; i < 8; ++i)
#pragma unroll
        for (int j = 0; j < 8; ++j) acc[i][j] = 0.0f;

    // prefetch tile 0
    float4 a0 = *(const float4*)(Aptr);
    float4 a1 = *(const float4*)(Aptr + (size_t)64 * lda);
    float4 b0 = *(const float4*)(Bptr);
    float4 b1 = *(const float4*)(Bptr + (size_t)64 * ldb);

    // store tile 0 into buffer 0 (transpose k-major)
    As[0][lk + 0][lr]      = a0.x; As[0][lk + 1][lr]      = a0.y; As[0][lk + 2][lr]      = a0.z; As[0][lk + 3][lr]      = a0.w;
    As[0][lk + 0][lr + 64] = a1.x; As[0][lk + 1][lr + 64] = a1.y; As[0][lk + 2][lr + 64] = a1.z; As[0][lk + 3][lr + 64] = a1.w;
    Bs[0][lk + 0][lr]      = b0.x; Bs[0][lk + 1][lr]      = b0.y; Bs[0][lk + 2][lr]      = b0.z; Bs[0][lk + 3][lr]      = b0.w;
    Bs[0][lk + 0][lr + 64] = b1.x; Bs[0][lk + 1][lr + 64] = b1.y; Bs[0][lk + 2][lr + 64] = b1.z; Bs[0][lk + 3][lr + 64] = b1.w;
    __syncthreads();

    int buf = 0;
    for (int k0 = 0; k0 < HH; k0 += BK) {
        const bool more = (k0 + BK) < HH;
        if (more) {
            a0 = *(const float4*)(Aptr + k0 + BK);
            a1 = *(const float4*)(Aptr + (size_t)64 * lda + k0 + BK);
            b0 = *(const float4*)(Bptr + k0 + BK);
            b1 = *(const float4*)(Bptr + (size_t)64 * ldb + k0 + BK);
        }
#pragma unroll
        for (int kk = 0; kk < BK; ++kk) {
            float4 av0 = *(const float4*)&As[buf][kk][ty * 4];
            float4 av1 = *(const float4*)&As[buf][kk][64 + ty * 4];
            float4 bv0 = *(const float4*)&Bs[buf][kk][tx * 4];
            float4 bv1 = *(const float4*)&Bs[buf][kk][64 + tx * 4];
            float a[8] = {av0.x, av0.y, av0.z, av0.w, av1.x, av1.y, av1.z, av1.w};
            float b[8] = {bv0.x, bv0.y, bv0.z, bv0.w, bv1.x, bv1.y, bv1.z, bv1.w};
#pragma unroll
            for (int i = 0; i < 8; ++i)
#pragma unroll
                for (int j = 0; j < 8; ++j) acc[i][j] += a[i] * b[j];
        }
        if (more) {
            const int nb = buf ^ 1;
            As[nb][lk + 0][lr]      = a0.x; As[nb][lk + 1][lr]      = a0.y; As[nb][lk + 2][lr]      = a0.z; As[nb][lk + 3][lr]      = a0.w;
            As[nb][lk + 0][lr + 64] = a1.x; As[nb][lk + 1][lr + 64] = a1.y; As[nb][lk + 2][lr + 64] = a1.z; As[nb][lk + 3][lr + 64] = a1.w;
            Bs[nb][lk + 0][lr]      = b0.x; Bs[nb][lk + 1][lr]      = b0.y; Bs[nb][lk + 2][lr]      = b0.z; Bs[nb][lk + 3][lr]      = b0.w;
            Bs[nb][lk + 0][lr + 64] = b1.x; Bs[nb][lk + 1][lr + 64] = b1.y; Bs[nb][lk + 2][lr + 64] = b1.z; Bs[nb][lk + 3][lr + 64] = b1.w;
        }
        __syncthreads();
        buf ^= 1;
    }

    // epilogue: four 4x4 quadrants, float4 stores
    float bvl[8];
#pragma unroll
    for (int j = 0; j < 4; ++j) {
        bvl[j]     = (MODE == 0) ? bias[n0 + tx * 4 + j]      : 0.0f;
        bvl[4 + j] = (MODE == 0) ? bias[n0 + 64 + tx * 4 + j] : 0.0f;
    }
#pragma unroll
    for (int i = 0; i < 8; ++i) {
        const int m = m0 + ((i < 4) ? (ty * 4 + i) : (64 + ty * 4 + (i - 4)));
        float4 o0, o1;
        o0.x = scale * acc[i][0] + bvl[0]; o0.y = scale * acc[i][1] + bvl[1];
        o0.z = scale * acc[i][2] + bvl[2]; o0.w = scale * acc[i][3] + bvl[3];
        o1.x = scale * acc[i][4] + bvl[4]; o1.y = scale * acc[i][5] + bvl[5];
        o1.z = scale * acc[i][6] + bvl[6]; o1.w = scale * acc[i][7] + bvl[7];
        *(float4*)(C + (size_t)m * ldc + n0 + tx * 4)      = o0;
        *(float4*)(C + (size_t)m * ldc + n0 + 64 + tx * 4) = o1;
    }
}

// ---------------- su[n] = C1 * dot(K[n], wq_load) ------------------------
__global__ void su_kernel() {
    int row = blockIdx.x * 8 + (threadIdx.x >> 5);
    int lane = threadIdx.x & 31;
    const float* kr = g_K + (size_t)row * HH;
    float acc = 0.0f;
    for (int i = lane; i < HH; i += 32) acc += kr[i] * g_wqload[i];
#pragma unroll
    for (int off = 16; off; off >>= 1) acc += __shfl_down_sync(0xffffffffu, acc, off);
    if (lane == 0) g_su[row] = C1 * acc;
}

// ---------------- sequential greedy decode (1 block, 256 threads) --------
// One __syncthreads per step: warp partials double-buffered; every thread
// redundantly reduces the 8 partials and updates its local state.
__global__ __launch_bounds__(256, 1)
void decode_kernel(const float* __restrict__ demands,
                   const int* __restrict__ cap_p,
                   const int* __restrict__ dep_p,
                   float* __restrict__ out) {
    const int tid = threadIdx.x;
    const int lane = tid & 31;
    const int warp = tid >> 5;
    const float cap = (float)(*cap_p);
    const int dep = *dep_p;
    const float NEG_INF = __int_as_float(0xff800000);

    __shared__ float s_dem[NN];      // demands cache (LDS hit instead of LDG)
    __shared__ float s_pv[2][8];
    __shared__ int   s_pi[2][8];

    // per-thread static state: 8 nodes each
    const int nbase = tid * 8;
    float d[8], su[8];
#pragma unroll
    for (int j = 0; j < 8; ++j) { d[j] = demands[nbase + j]; su[j] = g_su[nbase + j]; }
#pragma unroll
    for (int j = 0; j < 8; ++j) s_dem[nbase + j] = d[j];

    unsigned vis = 0;
    if ((dep >> 3) == tid) vis |= 1u << (dep & 7);
    float load = cap;
    int last = dep;

    if (tid == 0) out[0] = (float)dep;
    __syncthreads();

    for (int t = 0; t < TSTEPS; ++t) {
        const int buf = t & 1;
        const float sload = load / cap;
        const float4* prow = reinterpret_cast<const float4*>(g_P + (size_t)last * NN);
        float4 p0 = prow[tid * 2 + 0];
        float4 p1 = prow[tid * 2 + 1];
        float pv[8] = {p0.x, p0.y, p0.z, p0.w, p1.x, p1.y, p1.z, p1.w};

        float best = NEG_INF;
        int bi = NN;
#pragma unroll
        for (int j = 0; j < 8; ++j) {
            float v = pv[j] + sload * su[j];
            bool feas = (((vis >> j) & 1u) == 0u) && (d[j] <= load);
            if (feas && v > best) { best = v; bi = nbase + j; }   // ascending j: first-max kept
        }
        // warp argmax (tie -> lower index = jnp.argmax first-occurrence)
#pragma unroll
        for (int off = 16; off; off >>= 1) {
            float ov = __shfl_down_sync(0xffffffffu, best, off);
            int   oi = __shfl_down_sync(0xffffffffu, bi, off);
            if (ov > best || (ov == best && oi < bi)) { best = ov; bi = oi; }
        }
        if (lane == 0) { s_pv[buf][warp] = best; s_pi[buf][warp] = bi; }
        __syncthreads();

        // every thread reduces the 8 partials (ascending warp = ascending node
        // range, strict > keeps the lower index on ties)
        float v = NEG_INF;
        int i = NN;
#pragma unroll
        for (int w = 0; w < 8; ++w) {
            float wv = s_pv[buf][w];
            int   wi = s_pi[buf][w];
            if (wv > v) { v = wv; i = wi; }
        }
        const bool take = (i < NN);
        const int nxt = take ? i : dep;
        if (tid == 0) {
            out[1 + t] = (float)nxt;
            out[1 + TSTEPS + t] = take ? v : 0.0f;
        }
        const float nd = s_dem[take ? i : 0];
        load = take ? (load - nd) : cap;
        last = nxt;
        if (take && (i >> 3) == tid) vis |= 1u << (i & 7);
        // no second sync: next step writes s_pv[buf^1], read of s_pv[buf]
        // is protected by the next step's sync before buf is reused.
    }
}

// ---------------- launcher ----------------------------------------------
extern "C" void kernel_launch(void* const* d_in, const int* in_sizes, int n_in,
                              void* d_out, int out_size) {
    const float* E   = (const float*)d_in[0];   // node_emb [2048,1024]
    const float* dem = (const float*)d_in[1];   // demands  [2048]
    const float* Wq  = (const float*)d_in[2];   // [1024,1026]
    const float* bq  = (const float*)d_in[3];   // [1024]
    const float* Wk  = (const float*)d_in[4];   // [1024,1024]
    const float* bk  = (const float*)d_in[5];   // [1024]
    const int*   cap = (const int*)d_in[6];     // scalar
    const int*   dep = (const int*)d_in[7];     // scalar
    float* out = (float*)d_out;                 // tour[2305] ++ scores[2304] as f32

    pack_wq_kernel<<<(HH * HH + 255) / 256, 256>>>(Wq);

    dim3 gkq(HH / BN, NN / BM, 2);              // 8 x 16 x 2 (K and Q fused)
    gemm_kernel<0><<<gkq, 256>>>(E, Wk, bk, bq);
    su_kernel<<<NN / 8, 256>>>();               // g_su (needs g_K)

    dim3 gp(NN / BN, NN / BM);                  // 16 x 16
    gemm_kernel<1><<<gp, 256>>>(nullptr, nullptr, nullptr, nullptr); // g_P

    decode_kernel<<<1, 256>>>(dem, cap, dep, out);
}

// round 7
// speedup vs baseline: 1.5749x; 1.5696x over previous
#include <cuda_runtime.h>
#include <cstdint>

#define NN 2048
#define HH 1024
#define TSTEPS (NN + NN/8)   // 2304
#define C1 0.015625f          // ALPHA(0.5) / sqrt(1024)

// ---------------- static scratch (no allocations allowed) ----------------
__device__ float g_K[(size_t)NN * HH];       // 8 MB : K = E@Wk^T + bk
__device__ float g_Q[(size_t)NN * HH];       // 8 MB : Q = E@Wq1^T + bq
__device__ float g_P[(size_t)NN * NN];       // 16 MB: P = C1 * Q @ K^T
__device__ float g_Wq1[(size_t)HH * HH];     // 4 MB : packed Wq[:, :1024]
__device__ float g_wqload[HH];               // Wq[:, 1024]
__device__ float g_su[NN];                   // C1 * K @ wq_load

// ---------------- pack Wq (stride 1026 -> 1024, extract load column) -----
__global__ void pack_wq_kernel(const float* __restrict__ Wq) {
    int idx = blockIdx.x * blockDim.x + threadIdx.x;
    if (idx < HH * HH) {
        int i = idx >> 10;
        int h = idx & 1023;
        g_Wq1[idx] = Wq[i * (HH + 2) + h];
    }
    if (idx < HH) {
        g_wqload[idx] = Wq[idx * (HH + 2) + HH];
    }
}

// ---------------- NT GEMM: C = scale*(A@B^T) + bias[col] -----------------
#define BM 128
#define BN 128
#define BK 16
#define LDS_PAD 4

template<int MODE>
__global__ __launch_bounds__(256, 2)
void gemm_kernel(const float* __restrict__ Ein, const float* __restrict__ Wk,
                 const float* __restrict__ bk, const float* __restrict__ bq)
{
    const float* A; const float* B; const float* bias; float* C;
    int ldc; float scale;
    if (MODE == 0) {
        A = Ein;
        if (blockIdx.z == 0) { B = Wk;    bias = bk; C = g_K; }
        else                 { B = g_Wq1; bias = bq; C = g_Q; }
        ldc = HH; scale = 1.0f;
    } else {
        A = g_Q; B = g_K; bias = nullptr; C = g_P; ldc = NN; scale = C1;
    }
    const int lda = HH, ldb = HH;

    __shared__ float As[2][BK][BM + LDS_PAD];
    __shared__ float Bs[2][BK][BN + LDS_PAD];

    const int tid = threadIdx.x;
    const int m0 = blockIdx.y * BM;
    const int n0 = blockIdx.x * BN;
    const int tx = tid & 15;
    const int ty = tid >> 4;

    const int lr = tid >> 2;
    const int lk = (tid & 3) * 4;

    const float* Aptr = A + (size_t)(m0 + lr) * lda + lk;
    const float* Bptr = B + (size_t)(n0 + lr) * ldb + lk;

    float acc[8][8];
#pragma unroll
    for (int i = 0; i < 8; ++i)
#pragma unroll
        for (int j = 0; j < 8; ++j) acc[i][j] = 0.0f;

    float4 a0 = *(const float4*)(Aptr);
    float4 a1 = *(const float4*)(Aptr + (size_t)64 * lda);
    float4 b0 = *(const float4*)(Bptr);
    float4 b1 = *(const float4*)(Bptr + (size_t)64 * ldb);

    As[0][lk + 0][lr]      = a0.x; As[0][lk + 1][lr]      = a0.y; As[0][lk + 2][lr]      = a0.z; As[0][lk + 3][lr]      = a0.w;
    As[0][lk + 0][lr + 64] = a1.x; As[0][lk + 1][lr + 64] = a1.y; As[0][lk + 2][lr + 64] = a1.z; As[0][lk + 3][lr + 64] = a1.w;
    Bs[0][lk + 0][lr]      = b0.x; Bs[0][lk + 1][lr]      = b0.y; Bs[0][lk + 2][lr]      = b0.z; Bs[0][lk + 3][lr]      = b0.w;
    Bs[0][lk + 0][lr + 64] = b1.x; Bs[0][lk + 1][lr + 64] = b1.y; Bs[0][lk + 2][lr + 64] = b1.z; Bs[0][lk + 3][lr + 64] = b1.w;
    __syncthreads();

    int buf = 0;
    for (int k0 = 0; k0 < HH; k0 += BK) {
        const bool more = (k0 + BK) < HH;
        if (more) {
            a0 = *(const float4*)(Aptr + k0 + BK);
            a1 = *(const float4*)(Aptr + (size_t)64 * lda + k0 + BK);
            b0 = *(const float4*)(Bptr + k0 + BK);
            b1 = *(const float4*)(Bptr + (size_t)64 * ldb + k0 + BK);
        }
#pragma unroll
        for (int kk = 0; kk < BK; ++kk) {
            float4 av0 = *(const float4*)&As[buf][kk][ty * 4];
            float4 av1 = *(const float4*)&As[buf][kk][64 + ty * 4];
            float4 bv0 = *(const float4*)&Bs[buf][kk][tx * 4];
            float4 bv1 = *(const float4*)&Bs[buf][kk][64 + tx * 4];
            float a[8] = {av0.x, av0.y, av0.z, av0.w, av1.x, av1.y, av1.z, av1.w};
            float b[8] = {bv0.x, bv0.y, bv0.z, bv0.w, bv1.x, bv1.y, bv1.z, bv1.w};
#pragma unroll
            for (int i = 0; i < 8; ++i)
#pragma unroll
                for (int j = 0; j < 8; ++j) acc[i][j] += a[i] * b[j];
        }
        if (more) {
            const int nb = buf ^ 1;
            As[nb][lk + 0][lr]      = a0.x; As[nb][lk + 1][lr]      = a0.y; As[nb][lk + 2][lr]      = a0.z; As[nb][lk + 3][lr]      = a0.w;
            As[nb][lk + 0][lr + 64] = a1.x; As[nb][lk + 1][lr + 64] = a1.y; As[nb][lk + 2][lr + 64] = a1.z; As[nb][lk + 3][lr + 64] = a1.w;
            Bs[nb][lk + 0][lr]      = b0.x; Bs[nb][lk + 1][lr]      = b0.y; Bs[nb][lk + 2][lr]      = b0.z; Bs[nb][lk + 3][lr]      = b0.w;
            Bs[nb][lk + 0][lr + 64] = b1.x; Bs[nb][lk + 1][lr + 64] = b1.y; Bs[nb][lk + 2][lr + 64] = b1.z; Bs[nb][lk + 3][lr + 64] = b1.w;
        }
        __syncthreads();
        buf ^= 1;
    }

    float bvl[8];
#pragma unroll
    for (int j = 0; j < 4; ++j) {
        bvl[j]     = (MODE == 0) ? bias[n0 + tx * 4 + j]      : 0.0f;
        bvl[4 + j] = (MODE == 0) ? bias[n0 + 64 + tx * 4 + j] : 0.0f;
    }
#pragma unroll
    for (int i = 0; i < 8; ++i) {
        const int m = m0 + ((i < 4) ? (ty * 4 + i) : (64 + ty * 4 + (i - 4)));
        float4 o0, o1;
        o0.x = scale * acc[i][0] + bvl[0]; o0.y = scale * acc[i][1] + bvl[1];
        o0.z = scale * acc[i][2] + bvl[2]; o0.w = scale * acc[i][3] + bvl[3];
        o1.x = scale * acc[i][4] + bvl[4]; o1.y = scale * acc[i][5] + bvl[5];
        o1.z = scale * acc[i][6] + bvl[6]; o1.w = scale * acc[i][7] + bvl[7];
        *(float4*)(C + (size_t)m * ldc + n0 + tx * 4)      = o0;
        *(float4*)(C + (size_t)m * ldc + n0 + 64 + tx * 4) = o1;
    }
}

// ---------------- su[n] = C1 * dot(K[n], wq_load) ------------------------
__global__ void su_kernel() {
    int row = blockIdx.x * 8 + (threadIdx.x >> 5);
    int lane = threadIdx.x & 31;
    const float* kr = g_K + (size_t)row * HH;
    float acc = 0.0f;
    for (int i = lane; i < HH; i += 32) acc += kr[i] * g_wqload[i];
#pragma unroll
    for (int off = 16; off; off >>= 1) acc += __shfl_down_sync(0xffffffffu, acc, off);
    if (lane == 0) g_su[row] = C1 * acc;
}

// ---------------- sequential greedy decode (1 block, 256 threads) --------
// Latency-optimized chain: feasibility folded into dd (visited -> +inf, so
// one FSETP per node), FMNMX tree + eq-mask + ffs local argmax,
// REDUX.MAX.U32 warp argmax on order-preserving encoded floats,
// packed u64 keys + per-thread depth-3 tree for the cross-warp final.
// One __syncthreads per step (double-buffered partial keys).

__device__ __forceinline__ unsigned enc_f32(float f) {
    unsigned b = __float_as_uint(f);
    return b ^ ((unsigned)((int)b >> 31) | 0x80000000u);
}

#define ENC_NEGINF 0x007FFFFFu   // enc(-inf)

__global__ __launch_bounds__(256, 1)
void decode_kernel(const float* __restrict__ demands,
                   const int* __restrict__ cap_p,
                   const int* __restrict__ dep_p,
                   float* __restrict__ out) {
    const int tid = threadIdx.x;
    const int lane = tid & 31;
    const int warp = tid >> 5;
    const float cap = (float)(*cap_p);
    const int dep = *dep_p;
    const float NEG_INF = __int_as_float(0xff800000);
    const float POS_INF = __int_as_float(0x7f800000);

    __shared__ float s_dem[NN];                    // demands cache
    __shared__ unsigned long long s_key[2][8];     // per-warp packed partials

    // per-thread static state: 8 nodes each. dd = demand, +inf once visited.
    const int nbase = tid * 8;
    float dd[8], su[8];
#pragma unroll
    for (int j = 0; j < 8; ++j) {
        dd[j] = demands[nbase + j];
        su[j] = g_su[nbase + j];
        s_dem[nbase + j] = dd[j];
    }
    if ((dep >> 3) == tid) dd[dep & 7] = POS_INF;  // depot pre-visited

    float load = cap;
    float sload = load / cap;
    int last = dep;

    if (tid == 0) out[0] = (float)dep;
    __syncthreads();

    for (int t = 0; t < TSTEPS; ++t) {
        const int buf = t & 1;
        const float4* prow = reinterpret_cast<const float4*>(g_P + (size_t)last * NN);
        float4 p0 = prow[tid * 2 + 0];
        float4 p1 = prow[tid * 2 + 1];
        float pv[8] = {p0.x, p0.y, p0.z, p0.w, p1.x, p1.y, p1.z, p1.w};

        // masked scores (feasibility FSETPs depend only on dd/load -> issue
        // while the P-row LDG is in flight)
        float vm[8];
#pragma unroll
        for (int j = 0; j < 8; ++j)
            vm[j] = (dd[j] <= load) ? fmaf(sload, su[j], pv[j]) : NEG_INF;

        // local max: FMNMX tree (depth 3), then first-occurrence index via
        // parallel equality mask + ffs
        float m = fmaxf(fmaxf(fmaxf(vm[0], vm[1]), fmaxf(vm[2], vm[3])),
                        fmaxf(fmaxf(vm[4], vm[5]), fmaxf(vm[6], vm[7])));
        unsigned msk = 0;
#pragma unroll
        for (int j = 0; j < 8; ++j)
            msk |= (vm[j] == m) ? (1u << j) : 0u;
        const int bi = nbase + (__ffs(msk) - 1);
        const unsigned u = enc_f32(m);             // order-preserving

        // warp argmax: redux on value, ballot+shfl for min-index tiebreak
        // (lanes own ascending disjoint node ranges -> min lane = min index)
        const unsigned wmax = __reduce_max_sync(0xffffffffu, u);
        const unsigned ball = __ballot_sync(0xffffffffu, u == wmax);
        const int widx = __shfl_sync(0xffffffffu, bi, __ffs(ball) - 1);
        if (lane == 0)
            s_key[buf][warp] = ((unsigned long long)wmax << 32) |
                               (unsigned)(2047 - widx);
        __syncthreads();

        // cross-warp final: every thread reduces the 8 packed keys
        unsigned long long k0 = s_key[buf][0], k1 = s_key[buf][1];
        unsigned long long k2 = s_key[buf][2], k3 = s_key[buf][3];
        unsigned long long k4 = s_key[buf][4], k5 = s_key[buf][5];
        unsigned long long k6 = s_key[buf][6], k7 = s_key[buf][7];
        unsigned long long a01 = (k0 > k1) ? k0 : k1;
        unsigned long long a23 = (k2 > k3) ? k2 : k3;
        unsigned long long a45 = (k4 > k5) ? k4 : k5;
        unsigned long long a67 = (k6 > k7) ? k6 : k7;
        unsigned long long a03 = (a01 > a23) ? a01 : a23;
        unsigned long long a47 = (a45 > a67) ? a45 : a67;
        unsigned long long kk  = (a03 > a47) ? a03 : a47;

        const unsigned uf = (unsigned)(kk >> 32);
        const bool take = (uf != ENC_NEGINF);
        const int idx = 2047 - (int)(unsigned)(kk & 0xFFFFFFFFull);
        const int nxt = take ? idx : dep;

        const float nd = s_dem[take ? idx : 0];
        load = take ? (load - nd) : cap;
        sload = load / cap;
        last = nxt;
        if (take && (idx >> 3) == tid) dd[idx & 7] = POS_INF;

        if (tid == 0) {
            out[1 + t] = (float)nxt;
            unsigned dm = (uf & 0x80000000u) ? 0x80000000u : 0xFFFFFFFFu;
            out[1 + TSTEPS + t] = take ? __uint_as_float(uf ^ dm) : 0.0f;
        }
        // single barrier per step: next iteration writes s_key[buf^1];
        // s_key[buf] is not rewritten until after the next barrier.
    }
}

// ---------------- launcher ----------------------------------------------
extern "C" void kernel_launch(void* const* d_in, const int* in_sizes, int n_in,
                              void* d_out, int out_size) {
    const float* E   = (const float*)d_in[0];   // node_emb [2048,1024]
    const float* dem = (const float*)d_in[1];   // demands  [2048]
    const float* Wq  = (const float*)d_in[2];   // [1024,1026]
    const float* bq  = (const float*)d_in[3];   // [1024]
    const float* Wk  = (const float*)d_in[4];   // [1024,1024]
    const float* bk  = (const float*)d_in[5];   // [1024]
    const int*   cap = (const int*)d_in[6];     // scalar
    const int*   dep = (const int*)d_in[7];     // scalar
    float* out = (float*)d_out;                 // tour[2305] ++ scores[2304] as f32

    pack_wq_kernel<<<(HH * HH + 255) / 256, 256>>>(Wq);

    dim3 gkq(HH / BN, NN / BM, 2);              // K and Q fused
    gemm_kernel<0><<<gkq, 256>>>(E, Wk, bk, bq);
    su_kernel<<<NN / 8, 256>>>();               // g_su (needs g_K)

    dim3 gp(NN / BN, NN / BM);                  // 16 x 16
    gemm_kernel<1><<<gp, 256>>>(nullptr, nullptr, nullptr, nullptr); // g_P

    decode_kernel<<<1, 256>>>(dem, cap, dep, out);
}